// round 10
// baseline (speedup 1.0000x reference)
#include <cuda_runtime.h>
#include <math.h>
#include <stdint.h>

#define NL 6
#define NH 8
#define DM 512
#define DHS 64
#define NB 8
#define NT 1024
#define NF 32
#define NE 16
#define DFF 2048
#define NO 49
#define BT (NB*NT)
#define QKVS 1536
#define EPSV 1e-5f

// ---------------- scratch (device globals: no allocation allowed) ----------
__device__ float g_x  [BT*DM];
__device__ float g_xn [BT*DM];
__device__ float g_qkv[BT*QKVS];           // fused q|k|v, row stride 1536
__device__ float g_o  [BT*DM];
__device__ float g_h1 [BT*DFF];
__device__ float g_scores[BT];
__device__ float g_aw[BT];
__device__ float g_part[NB*8*DM];
__device__ float g_Wqkv[NL*DM*QKVS];       // repacked+rounded [l][d][w*512+h*64+e]
__device__ float g_WoR [NL*DM*DM];
__device__ float g_W1R [NL*DM*DFF];
__device__ float g_W2R [NL*DFF*DM];

// ---------------- tf32 helpers ----------------
__device__ __forceinline__ uint32_t f2tf(float x) {
    uint32_t r;
    asm("cvt.rna.tf32.f32 %0, %1;" : "=r"(r) : "f"(x));
    return r;
}
__device__ __forceinline__ float tff(float x) { return __uint_as_float(f2tf(x)); }

__device__ __forceinline__ void mma_tf32(float c[4], const uint32_t a[4], const uint32_t b[2]) {
    asm volatile(
        "mma.sync.aligned.m16n8k8.row.col.f32.tf32.tf32.f32 "
        "{%0,%1,%2,%3}, {%4,%5,%6,%7}, {%8,%9}, {%0,%1,%2,%3};"
        : "+f"(c[0]), "+f"(c[1]), "+f"(c[2]), "+f"(c[3])
        : "r"(a[0]), "r"(a[1]), "r"(a[2]), "r"(a[3]), "r"(b[0]), "r"(b[1]));
}

__device__ __forceinline__ void cpa16(uint32_t s, const void* g) {
    asm volatile("cp.async.cg.shared.global [%0], [%1], 16;\n" :: "r"(s), "l"(g));
}
__device__ __forceinline__ void cpcommit() {
    asm volatile("cp.async.commit_group;\n" ::: "memory");
}

// ---------------- reductions ----------------
__device__ __forceinline__ float blockReduceSum(float v, float* sbuf) {
    int lane = threadIdx.x & 31, wid = threadIdx.x >> 5;
    #pragma unroll
    for (int o = 16; o > 0; o >>= 1) v += __shfl_down_sync(0xffffffffu, v, o);
    if (lane == 0) sbuf[wid] = v;
    __syncthreads();
    int nw = blockDim.x >> 5;
    v = (threadIdx.x < nw) ? sbuf[threadIdx.x] : 0.f;
    if (wid == 0) {
        #pragma unroll
        for (int o = 16; o > 0; o >>= 1) v += __shfl_down_sync(0xffffffffu, v, o);
        if (lane == 0) sbuf[0] = v;
    }
    __syncthreads();
    float r = sbuf[0];
    __syncthreads();
    return r;
}

__device__ __forceinline__ float blockReduceMax(float v, float* sbuf) {
    int lane = threadIdx.x & 31, wid = threadIdx.x >> 5;
    #pragma unroll
    for (int o = 16; o > 0; o >>= 1) v = fmaxf(v, __shfl_down_sync(0xffffffffu, v, o));
    if (lane == 0) sbuf[wid] = v;
    __syncthreads();
    int nw = blockDim.x >> 5;
    v = (threadIdx.x < nw) ? sbuf[threadIdx.x] : -3.0e38f;
    if (wid == 0) {
        #pragma unroll
        for (int o = 16; o > 0; o >>= 1) v = fmaxf(v, __shfl_down_sync(0xffffffffu, v, o));
        if (lane == 0) sbuf[0] = v;
    }
    __syncthreads();
    float r = sbuf[0];
    __syncthreads();
    return r;
}

// ---------------- weight repack (with tf32 rounding) ----------------
// g_Wqkv[l][d][w*512 + h*64 + e] = round(W_w[l][h][d][e])
__global__ void repack_qkv_kernel(const float* __restrict__ Wq,
                                  const float* __restrict__ Wk,
                                  const float* __restrict__ Wv,
                                  float* __restrict__ out) {
    long long idx = (long long)blockIdx.x * 256 + threadIdx.x;  // NL*DM*1536
    int col = (int)(idx % QKVS);
    long long ld = idx / QKVS;
    int d = (int)(ld & 511), l = (int)(ld >> 9);
    int w = col >> 9, n = col & 511;
    int h = n >> 6, e = n & 63;
    const float* W = (w == 0) ? Wq : (w == 1) ? Wk : Wv;
    out[idx] = tff(W[(((long long)(l * NH + h)) * DM + d) * DHS + e]);
}

__global__ void roundcopy_kernel(const float* __restrict__ in,
                                 float* __restrict__ out, int n4) {
    int i = blockIdx.x * 256 + threadIdx.x;
    if (i < n4) {
        float4 v = ((const float4*)in)[i];
        v.x = tff(v.x); v.y = tff(v.y); v.z = tff(v.z); v.w = tff(v.w);
        ((float4*)out)[i] = v;
    }
}

// ---------------- embed + posenc ----------------
__global__ void embed_kernel(const int* __restrict__ code,
                             const float* __restrict__ emb,
                             float* __restrict__ x) {
    int bt = blockIdx.x;
    int t  = bt & (NT - 1);
    int d0 = threadIdx.x * 4;
    const int* crow = code + (long long)bt * NF;
    float4 out;
    float* po = (float*)&out;
    #pragma unroll
    for (int j = 0; j < 4; j++) {
        int d = d0 + j;
        int f = d >> 4, e = d & 15;
        int c = crow[f];
        float df  = expf(-(float)(d & ~1) * (9.210340371976184f / 512.0f));
        float ang = (float)t * df;
        float pe  = (d & 1) ? cosf(ang) : sinf(ang);
        po[j] = emb[c * NE + e] + pe;
    }
    *(float4*)(x + (long long)bt * DM + d0) = out;
}

// ---------------- layernorm (optional tf32-rounded output) ----------------
__global__ void ln_kernel(const float* __restrict__ in,
                          const float* __restrict__ g,
                          const float* __restrict__ b,
                          float* __restrict__ out, int rnd) {
    __shared__ float red[32];
    int bt = blockIdx.x;
    int tid = threadIdx.x;
    float4 v = *(const float4*)(in + (long long)bt * DM + tid * 4);
    float s = v.x + v.y + v.z + v.w;
    s = blockReduceSum(s, red);
    float mean = s * (1.0f / DM);
    float d0 = v.x - mean, d1 = v.y - mean, d2 = v.z - mean, d3 = v.w - mean;
    float s2 = d0*d0 + d1*d1 + d2*d2 + d3*d3;
    s2 = blockReduceSum(s2, red);
    float inv = rsqrtf(s2 * (1.0f / DM) + EPSV);
    float4 gg = *(const float4*)(g + tid * 4);
    float4 bb = *(const float4*)(b + tid * 4);
    float4 o;
    o.x = d0 * inv * gg.x + bb.x;
    o.y = d1 * inv * gg.y + bb.y;
    o.z = d2 * inv * gg.z + bb.z;
    o.w = d3 * inv * gg.w + bb.w;
    if (rnd) { o.x = tff(o.x); o.y = tff(o.y); o.z = tff(o.z); o.w = tff(o.w); }
    *(float4*)(out + (long long)bt * DM + tid * 4) = o;
}

// ---------------- TF32 tensor-core GEMM ----------------
// 128x128 CTA tile, 4 warps of 64x64, BK=32, 3-stage cp.async pipeline.
// Inputs must be tf32-rounded already (round-at-producer).
// flags: 2=accumulate, 4=gelu, 8=bias, 16=round output.
#define AP 36
#define BP 136
#define SMEM_G ((3*128*AP + 3*32*BP) * 4)   // 107520 bytes

__global__ void __launch_bounds__(128, 2)
gemm_tc_kernel(const float* __restrict__ A, const float* __restrict__ Bm,
               const float* __restrict__ bias, float* __restrict__ C,
               int K, int lda, int ldb, int ldc,
               int flags, float alpha) {
    extern __shared__ float smem[];
    float* Asm = smem;                    // 3 x [128][AP]
    float* Bsm = smem + 3 * 128 * AP;     // 3 x [32][BP]

    int m0 = blockIdx.y * 128;
    int n0 = blockIdx.x * 128;

    int tid = threadIdx.x, lane = tid & 31, warp = tid >> 5;
    int wm = warp & 1, wn = warp >> 1;    // 2x2 warps of 64x64
    int grp = lane >> 2, qid = lane & 3;

    // ---- load geometry: 8 cp16 each for A and B per thread
    int am_ = tid >> 3;                   // 0..15
    int ak_ = (tid & 7) << 2;             // 0,4,..28
    const float* gA = A + (long long)(m0 + am_) * lda + ak_;
    uint32_t dAoff[8]; int aG[8];
    #pragma unroll
    for (int i = 0; i < 8; i++) {
        dAoff[i] = (uint32_t)(((am_ + 16 * i) * AP + ak_) * 4);
        aG[i] = 16 * i * lda;
    }
    int bk_ = tid >> 5;                   // 0..3
    int bn_ = (tid & 31) << 2;            // 0..124
    const float* gB = Bm + (long long)bk_ * ldb + n0 + bn_;
    uint32_t dBoff[8]; int bG[8];
    #pragma unroll
    for (int i = 0; i < 8; i++) {
        dBoff[i] = (uint32_t)(((bk_ + 4 * i) * BP + bn_) * 4);
        bG[i] = 4 * i * ldb;
    }

    uint32_t smA = (uint32_t)__cvta_generic_to_shared(Asm);
    uint32_t smB = (uint32_t)__cvta_generic_to_shared(Bsm);
    constexpr uint32_t SZA = 128 * AP * 4;
    constexpr uint32_t SZB = 32 * BP * 4;

    auto load_tile = [&](int st, int k0) {
        uint32_t bA = smA + st * SZA;
        uint32_t bB = smB + st * SZB;
        #pragma unroll
        for (int i = 0; i < 8; i++)
            cpa16(bA + dAoff[i], gA + k0 + aG[i]);
        int bko = k0 * ldb;
        #pragma unroll
        for (int i = 0; i < 8; i++)
            cpa16(bB + dBoff[i], gB + bko + bG[i]);
    };

    float acc[4][8][4];
    #pragma unroll
    for (int i = 0; i < 4; i++)
        #pragma unroll
        for (int j = 0; j < 8; j++)
            #pragma unroll
            for (int r = 0; r < 4; r++) acc[i][j][r] = 0.f;

    load_tile(0, 0);  cpcommit();
    load_tile(1, 32); cpcommit();         // K >= 64 always

    int aoff = (wm * 64 + grp) * AP + qid;
    int boff = qid * BP + wn * 64 + grp;

    int s = 0;
    for (int k0 = 0; k0 < K; k0 += 32) {
        asm volatile("cp.async.wait_group 1;\n" ::: "memory");
        __syncthreads();
        if (k0 + 64 < K) {
            int s2 = (s + 2) % 3;
            load_tile(s2, k0 + 64);
        }
        cpcommit();

        const uint32_t* uA = (const uint32_t*)(Asm + s * 128 * AP) + aoff;
        const uint32_t* uB = (const uint32_t*)(Bsm + s * 32 * BP) + boff;
        #pragma unroll
        for (int ks = 0; ks < 4; ks++) {
            int kk = ks * 8;
            uint32_t af[4][4], bf[8][2];
            #pragma unroll
            for (int i = 0; i < 4; i++) {
                af[i][0] = uA[(i * 16    ) * AP + kk    ];
                af[i][1] = uA[(i * 16 + 8) * AP + kk    ];
                af[i][2] = uA[(i * 16    ) * AP + kk + 4];
                af[i][3] = uA[(i * 16 + 8) * AP + kk + 4];
            }
            #pragma unroll
            for (int j = 0; j < 8; j++) {
                bf[j][0] = uB[ kk      * BP + j * 8];
                bf[j][1] = uB[(kk + 4) * BP + j * 8];
            }
            #pragma unroll
            for (int i = 0; i < 4; i++)
                #pragma unroll
                for (int j = 0; j < 8; j++)
                    mma_tf32(acc[i][j], af[i], bf[j]);
        }
        s = (s == 2) ? 0 : s + 1;
    }

    // ---- epilogue
    bool accum = (flags & 2), doGelu = (flags & 4), hasBias = (flags & 8), rnd = (flags & 16);
    #pragma unroll
    for (int i = 0; i < 4; i++) {
        #pragma unroll
        for (int j = 0; j < 8; j++) {
            int r0  = m0 + wm * 64 + i * 16 + grp;
            int col = n0 + wn * 64 + j * 8 + qid * 2;
            float bv0 = 0.f, bv1 = 0.f;
            if (hasBias) { bv0 = bias[col]; bv1 = bias[col + 1]; }
            #pragma unroll
            for (int h = 0; h < 2; h++) {
                int r = r0 + h * 8;
                float v0 = acc[i][j][h * 2 + 0] * alpha + bv0;
                float v1 = acc[i][j][h * 2 + 1] * alpha + bv1;
                if (doGelu) {
                    v0 = 0.5f * v0 * (1.0f + erff(v0 * 0.70710678118654752f));
                    v1 = 0.5f * v1 * (1.0f + erff(v1 * 0.70710678118654752f));
                }
                if (rnd) { v0 = tff(v0); v1 = tff(v1); }
                float* p = C + (long long)r * ldc + col;
                if (accum) {
                    float2 old = *(float2*)p;
                    v0 += old.x; v1 += old.y;
                }
                *(float2*)p = make_float2(v0, v1);
            }
        }
    }
}

// ---------------- fused flash attention ----------------
// qkv layout: [b*NT + t][1536]: q at col h*64, k at 512+h*64, v at 1024+h*64.
// o layout: [b*NT + t][512] at col h*64. One CTA = (b, h, 128-row q-tile).
#define FQP 68
#define FVP 72
#define FA_SMEM ((128*FQP + 2*64*FQP + 2*64*FVP + 128*FQP) * 4)

__global__ void __launch_bounds__(256, 1)
flash_attn_kernel(const float* __restrict__ qkv, const int* __restrict__ lengths,
                  float* __restrict__ o) {
    extern __shared__ float fsm[];
    float* Qs = fsm;                       // [128][FQP]
    float* Ks = Qs + 128 * FQP;            // [2][64][FQP]
    float* Vs = Ks + 2 * 64 * FQP;         // [2][64][FVP]
    float* Ps = Vs + 2 * 64 * FVP;         // [128][FQP]

    int b = blockIdx.z, h = blockIdx.y, qt = blockIdx.x;
    int len = lengths[b];
    int tid = threadIdx.x, lane = tid & 31, warp = tid >> 5;
    int grp = lane >> 2, qid = lane & 3;
    int w16 = warp * 16;

    const float* Qg = qkv + ((long long)(b * NT + qt * 128)) * QKVS + h * DHS;
    const float* Kg = qkv + ((long long)b * NT) * QKVS + 512 + h * DHS;
    const float* Vg = qkv + ((long long)b * NT) * QKVS + 1024 + h * DHS;

    #pragma unroll
    for (int i = 0; i < 8; i++) {
        int cid = i * 256 + tid;
        int r = cid >> 4, c = (cid & 15) << 2;
        cpa16((uint32_t)__cvta_generic_to_shared(&Qs[r * FQP + c]),
              Qg + (long long)r * QKVS + c);
    }
    auto loadKV = [&](int buf, int sb) {
        int s0 = sb * 64;
        #pragma unroll
        for (int i = 0; i < 4; i++) {
            int cid = i * 256 + tid;
            int ss = cid >> 4, c = (cid & 15) << 2;
            const float* kg = Kg + (long long)(s0 + ss) * QKVS + c;
            const float* vg = Vg + (long long)(s0 + ss) * QKVS + c;
            cpa16((uint32_t)__cvta_generic_to_shared(&Ks[(buf * 64 + ss) * FQP + c]), kg);
            cpa16((uint32_t)__cvta_generic_to_shared(&Vs[(buf * 64 + ss) * FVP + c]), vg);
        }
    };

    int nsb = (len + 63) >> 6;
    loadKV(0, 0);
    cpcommit();

    float m_[2] = {-1e30f, -1e30f};
    float l_[2] = {0.f, 0.f};
    float oacc[8][4];
    #pragma unroll
    for (int j = 0; j < 8; j++) { oacc[j][0]=oacc[j][1]=oacc[j][2]=oacc[j][3]=0.f; }

    for (int sb = 0; sb < nsb; sb++) {
        asm volatile("cp.async.wait_group 0;\n" ::: "memory");
        __syncthreads();
        int buf = sb & 1;
        if (sb + 1 < nsb) { loadKV(buf ^ 1, sb + 1); cpcommit(); }

        float sacc[8][4];
        #pragma unroll
        for (int j = 0; j < 8; j++) { sacc[j][0]=sacc[j][1]=sacc[j][2]=sacc[j][3]=0.f; }
        const uint32_t* uQ = (const uint32_t*)Qs;
        const uint32_t* uK = (const uint32_t*)(Ks + buf * 64 * FQP);
        #pragma unroll
        for (int ks = 0; ks < 8; ks++) {
            int kk = ks * 8;
            uint32_t af[4];
            af[0] = uQ[(w16 + grp    ) * FQP + kk + qid];
            af[1] = uQ[(w16 + grp + 8) * FQP + kk + qid];
            af[2] = uQ[(w16 + grp    ) * FQP + kk + qid + 4];
            af[3] = uQ[(w16 + grp + 8) * FQP + kk + qid + 4];
            #pragma unroll
            for (int j = 0; j < 8; j++) {
                uint32_t bf[2];
                bf[0] = uK[(j * 8 + grp) * FQP + kk + qid];
                bf[1] = uK[(j * 8 + grp) * FQP + kk + qid + 4];
                mma_tf32(sacc[j], af, bf);
            }
        }

        int s0 = sb * 64;
        #pragma unroll
        for (int hh = 0; hh < 2; hh++) {
            float mx = -1e30f;
            #pragma unroll
            for (int j = 0; j < 8; j++) {
                #pragma unroll
                for (int c = 0; c < 2; c++) {
                    float val = sacc[j][hh * 2 + c] * 0.125f;
                    if (s0 + j * 8 + qid * 2 + c >= len) val = -1e30f;
                    sacc[j][hh * 2 + c] = val;
                    mx = fmaxf(mx, val);
                }
            }
            mx = fmaxf(mx, __shfl_xor_sync(0xffffffffu, mx, 1));
            mx = fmaxf(mx, __shfl_xor_sync(0xffffffffu, mx, 2));
            float mn = fmaxf(m_[hh], mx);
            float sc = __expf(m_[hh] - mn);
            float rs = 0.f;
            #pragma unroll
            for (int j = 0; j < 8; j++) {
                #pragma unroll
                for (int c = 0; c < 2; c++) {
                    float p = __expf(sacc[j][hh * 2 + c] - mn);
                    sacc[j][hh * 2 + c] = p;
                    rs += p;
                }
            }
            rs += __shfl_xor_sync(0xffffffffu, rs, 1);
            rs += __shfl_xor_sync(0xffffffffu, rs, 2);
            l_[hh] = l_[hh] * sc + rs;
            m_[hh] = mn;
            #pragma unroll
            for (int j = 0; j < 8; j++) {
                oacc[j][hh * 2 + 0] *= sc;
                oacc[j][hh * 2 + 1] *= sc;
            }
        }

        #pragma unroll
        for (int j = 0; j < 8; j++) {
            *(float2*)&Ps[(w16 + grp    ) * FQP + j * 8 + qid * 2] =
                make_float2(tff(sacc[j][0]), tff(sacc[j][1]));
            *(float2*)&Ps[(w16 + grp + 8) * FQP + j * 8 + qid * 2] =
                make_float2(tff(sacc[j][2]), tff(sacc[j][3]));
        }
        __syncwarp();
        const uint32_t* uP = (const uint32_t*)Ps;
        const uint32_t* uV = (const uint32_t*)(Vs + buf * 64 * FVP);
        #pragma unroll
        for (int ks = 0; ks < 8; ks++) {
            int kk = ks * 8;
            uint32_t af[4];
            af[0] = uP[(w16 + grp    ) * FQP + kk + qid];
            af[1] = uP[(w16 + grp + 8) * FQP + kk + qid];
            af[2] = uP[(w16 + grp    ) * FQP + kk + qid + 4];
            af[3] = uP[(w16 + grp + 8) * FQP + kk + qid + 4];
            #pragma unroll
            for (int j = 0; j < 8; j++) {
                uint32_t bf[2];
                bf[0] = uV[(kk + qid    ) * FVP + j * 8 + grp];
                bf[1] = uV[(kk + qid + 4) * FVP + j * 8 + grp];
                mma_tf32(oacc[j], af, bf);
            }
        }
    }

    int tl0 = qt * 128 + w16 + grp;
    float inv0 = 1.0f / l_[0], inv1 = 1.0f / l_[1];
    bool z0 = (tl0 >= len), z1 = (tl0 + 8 >= len);
    float* Og = o + ((long long)(b * NT + tl0)) * DM + h * DHS;
    #pragma unroll
    for (int j = 0; j < 8; j++) {
        int c = j * 8 + qid * 2;
        float2 v0, v1;
        v0.x = z0 ? 0.f : tff(oacc[j][0] * inv0);
        v0.y = z0 ? 0.f : tff(oacc[j][1] * inv0);
        v1.x = z1 ? 0.f : tff(oacc[j][2] * inv1);
        v1.y = z1 ? 0.f : tff(oacc[j][3] * inv1);
        *(float2*)(Og + c) = v0;
        *(float2*)(Og + (long long)8 * DM + c) = v1;
    }
}

// ---------------- pooling ----------------
__global__ void score_kernel(const float* __restrict__ xn,
                             const float* __restrict__ attn_w,
                             const float* __restrict__ attn_b,
                             float* __restrict__ scores) {
    __shared__ float red[32];
    int bt = blockIdx.x, tid = threadIdx.x;
    float4 xv = *(const float4*)(xn + (long long)bt * DM + tid * 4);
    float4 wv = *(const float4*)(attn_w + tid * 4);
    float s = xv.x*wv.x + xv.y*wv.y + xv.z*wv.z + xv.w*wv.w;
    s = blockReduceSum(s, red);
    if (tid == 0) scores[bt] = s + attn_b[0];
}

__global__ void pool_softmax_kernel(const float* __restrict__ scores,
                                    const int* __restrict__ lengths,
                                    float* __restrict__ aw) {
    __shared__ float red[32];
    int b = blockIdx.x, t = threadIdx.x;
    int len = lengths[b];
    float s = (t < len) ? scores[b * NT + t] : -3.0e38f;
    float m = blockReduceMax(s, red);
    float e = (t < len) ? expf(s - m) : 0.f;
    float sum = blockReduceSum(e, red);
    aw[b * NT + t] = e / sum;
}

__global__ void pool_sum_kernel(const float* __restrict__ xn,
                                const float* __restrict__ aw,
                                float* __restrict__ part) {
    int b = blockIdx.y, c = blockIdx.x, d = threadIdx.x;
    float acc = 0.f;
    int t0 = c * 128;
    for (int t = t0; t < t0 + 128; t++)
        acc += aw[b * NT + t] * xn[((long long)b * NT + t) * DM + d];
    part[(b * 8 + c) * DM + d] = acc;
}

__global__ void logits_kernel(const float* __restrict__ part,
                              const float* __restrict__ head_w,
                              const float* __restrict__ head_b,
                              float* __restrict__ out) {
    __shared__ float summ[DM];
    int b = blockIdx.x, o = threadIdx.x;
    for (int d = o; d < DM; d += 64) {
        float s = 0.f;
        for (int c = 0; c < 8; c++) s += part[(b * 8 + c) * DM + d];
        summ[d] = s;
    }
    __syncthreads();
    if (o < NO) {
        float acc = head_b[o];
        for (int d = 0; d < DM; d++) acc += summ[d] * head_w[d * NO + o];
        out[b * NO + o] = acc;
    }
}

// ---------------- host wrapper ----------------
static void gemm(const float* A, const float* B, const float* bias, float* C,
                 int M, int N, int K, int lda, int ldb, int ldc,
                 int flags, float alpha) {
    dim3 grid(N / 128, M / 128);
    gemm_tc_kernel<<<grid, 128, SMEM_G>>>(A, B, bias, C, K, lda, ldb, ldc, flags, alpha);
}

extern "C" void kernel_launch(void* const* d_in, const int* in_sizes, int n_in,
                              void* d_out, int out_size) {
    const int*   code    = (const int*)  d_in[0];
    const int*   lengths = (const int*)  d_in[1];
    const float* emb     = (const float*)d_in[2];
    const float* Wq      = (const float*)d_in[3];
    const float* Wk      = (const float*)d_in[4];
    const float* Wv      = (const float*)d_in[5];
    const float* Wo      = (const float*)d_in[6];
    const float* bo      = (const float*)d_in[7];
    const float* W1      = (const float*)d_in[8];
    const float* b1      = (const float*)d_in[9];
    const float* W2      = (const float*)d_in[10];
    const float* b2      = (const float*)d_in[11];
    const float* ln1_g   = (const float*)d_in[12];
    const float* ln1_b   = (const float*)d_in[13];
    const float* ln2_g   = (const float*)d_in[14];
    const float* ln2_b   = (const float*)d_in[15];
    const float* lnf_g   = (const float*)d_in[16];
    const float* lnf_b   = (const float*)d_in[17];
    const float* attn_w  = (const float*)d_in[18];
    const float* attn_b  = (const float*)d_in[19];
    const float* head_w  = (const float*)d_in[20];
    const float* head_b  = (const float*)d_in[21];
    float* out = (float*)d_out;

    cudaFuncSetAttribute(gemm_tc_kernel,
                         cudaFuncAttributeMaxDynamicSharedMemorySize, SMEM_G);
    cudaFuncSetAttribute(flash_attn_kernel,
                         cudaFuncAttributeMaxDynamicSharedMemorySize, FA_SMEM);

    float *x, *xn, *qkv, *o, *h1, *scr, *aw, *part;
    float *Wqkv, *WoR, *W1R, *W2R;
    cudaGetSymbolAddress((void**)&x,   g_x);
    cudaGetSymbolAddress((void**)&xn,  g_xn);
    cudaGetSymbolAddress((void**)&qkv, g_qkv);
    cudaGetSymbolAddress((void**)&o,   g_o);
    cudaGetSymbolAddress((void**)&h1,  g_h1);
    cudaGetSymbolAddress((void**)&scr, g_scores);
    cudaGetSymbolAddress((void**)&aw,  g_aw);
    cudaGetSymbolAddress((void**)&part,g_part);
    cudaGetSymbolAddress((void**)&Wqkv,g_Wqkv);
    cudaGetSymbolAddress((void**)&WoR, g_WoR);
    cudaGetSymbolAddress((void**)&W1R, g_W1R);
    cudaGetSymbolAddress((void**)&W2R, g_W2R);

    // repack + round all weights
    repack_qkv_kernel<<<NL * DM * QKVS / 256, 256>>>(Wq, Wk, Wv, Wqkv);
    roundcopy_kernel<<<(NL*DM*DM/4 + 255)/256, 256>>>(Wo, WoR, NL*DM*DM/4);
    roundcopy_kernel<<<(NL*DM*DFF/4 + 255)/256, 256>>>(W1, W1R, NL*DM*DFF/4);
    roundcopy_kernel<<<(NL*DFF*DM/4 + 255)/256, 256>>>(W2, W2R, NL*DFF*DM/4);

    embed_kernel<<<BT, 128>>>(code, emb, x);

    for (int l = 0; l < NL; l++) {
        const float* Wql = Wqkv + (long long)l * DM * QKVS;
        const float* Wol = WoR + (long long)l * DM * DM;
        const float* W1l = W1R + (long long)l * DM * DFF;
        const float* W2l = W2R + (long long)l * DFF * DM;

        ln_kernel<<<BT, 128>>>(x, ln1_g + l * DM, ln1_b + l * DM, xn, 1);

        // qkv = round(xn @ Wqkv)  — single fused GEMM, N=1536
        gemm(xn, Wql, nullptr, qkv, BT, QKVS, DM, DM, QKVS, QKVS, 16, 1.0f);

        // fused attention
        flash_attn_kernel<<<dim3(NT / 128, NH, NB), 256, FA_SMEM>>>(qkv, lengths, o);

        // x += o @ Wo + bo
        gemm(o, Wol, bo + l * DM, x, BT, DM, DM, DM, DM, DM, 2 | 8, 1.0f);

        ln_kernel<<<BT, 128>>>(x, ln2_g + l * DM, ln2_b + l * DM, xn, 1);

        // h1 = round(gelu(xn @ W1 + b1))
        gemm(xn, W1l, b1 + l * DFF, h1, BT, DFF, DM, DM, DFF, DFF, 4 | 8 | 16, 1.0f);

        // x += h1 @ W2 + b2
        gemm(h1, W2l, b2 + l * DM, x, BT, DM, DFF, DFF, DM, DM, 2 | 8, 1.0f);
    }

    ln_kernel<<<BT, 128>>>(x, lnf_g, lnf_b, xn, 0);
    score_kernel<<<BT, 128>>>(xn, attn_w, attn_b, scr);
    pool_softmax_kernel<<<NB, 1024>>>(scr, lengths, aw);
    pool_sum_kernel<<<dim3(8, NB), 512>>>(xn, aw, part);
    logits_kernel<<<NB, 64>>>(part, head_w, head_b, out);
}